// round 3
// baseline (speedup 1.0000x reference)
#include <cuda_runtime.h>

#define B_   32
#define T_   1024
#define C_   128
#define EPS_ 1e-5f
#define SCL  0.08838834764831845f   // 1/sqrt(128)

// Scratch (zero-initialized at module load; invalid padded slots never written,
// valid slots rewritten with identical values each launch -> deterministic).
__device__ float g_padded[B_ * T_ * C_];   // 16 MB
__device__ float g_m[B_ * T_];
__device__ float g_invd[B_ * T_];

// ---------------------------------------------------------------------------
// K1: h = leaky(BN(concat(x_temp, x_stat[bidx]) @ W1^T + b1)), scatter to padded
// BM=64 rows, full 128 out-cols, 256 threads, 4x8 microtile, BK=32 chunks.
// ---------------------------------------------------------------------------
__global__ void k1_kernel(const float* __restrict__ x_temp, const float* __restrict__ x_stat,
                          const int* __restrict__ bidx, const int* __restrict__ pidx,
                          const float* __restrict__ W1, const float* __restrict__ b1,
                          const float* __restrict__ g1, const float* __restrict__ be1,
                          const float* __restrict__ mu1, const float* __restrict__ v1,
                          int N) {
    __shared__ float Xt[32 * 68];    // [k][row], pitch 68
    __shared__ float Ws[32 * 132];   // [k][col], pitch 132
    const int n0  = blockIdx.x * 64;
    const int tid = threadIdx.x;
    const int ty  = tid >> 4, tx = tid & 15;
    const int r0  = ty * 4, c0 = tx * 8;

    float acc[4][8];
#pragma unroll
    for (int i = 0; i < 4; i++)
#pragma unroll
        for (int j = 0; j < 8; j++) acc[i][j] = 0.f;

    for (int kt = 0; kt < 192; kt += 32) {
        __syncthreads();
        // load X tile (transposed): rows n0..n0+63, k = kt..kt+31
#pragma unroll
        for (int it = 0; it < 8; it++) {
            int idx = tid + it * 256;          // 64*32 = 2048
            int k = idx & 31, r = idx >> 5;
            int n = n0 + r, kg = kt + k;
            float v = 0.f;
            if (n < N)
                v = (kg < 128) ? x_temp[(size_t)n * 128 + kg]
                               : x_stat[bidx[n] * 64 + (kg - 128)];
            Xt[k * 68 + r] = v;
        }
        // load W tile (transposed): 128 cols x 32 k
#pragma unroll
        for (int it = 0; it < 16; it++) {
            int idx = tid + it * 256;          // 128*32 = 4096
            int k = idx & 31, c = idx >> 5;
            Ws[k * 132 + c] = W1[c * 192 + kt + k];
        }
        __syncthreads();
#pragma unroll 8
        for (int k = 0; k < 32; k++) {
            float4 xv = *(const float4*)&Xt[k * 68 + r0];
            float4 w0 = *(const float4*)&Ws[k * 132 + c0];
            float4 w1 = *(const float4*)&Ws[k * 132 + c0 + 4];
            float xa[4] = {xv.x, xv.y, xv.z, xv.w};
            float wb[8] = {w0.x, w0.y, w0.z, w0.w, w1.x, w1.y, w1.z, w1.w};
#pragma unroll
            for (int i = 0; i < 4; i++)
#pragma unroll
                for (int j = 0; j < 8; j++) acc[i][j] += xa[i] * wb[j];
        }
    }

    // epilogue: fold bias + BN, leaky, scatter
    float sc[8], bs[8];
#pragma unroll
    for (int j = 0; j < 8; j++) {
        int c = c0 + j;
        float s = g1[c] * rsqrtf(v1[c] + EPS_);
        sc[j] = s;
        bs[j] = (b1[c] - mu1[c]) * s + be1[c];
    }
#pragma unroll
    for (int i = 0; i < 4; i++) {
        int n = n0 + r0 + i;
        if (n < N) {
            int bb = bidx[n], t = pidx[n];
            float r[8];
#pragma unroll
            for (int j = 0; j < 8; j++) {
                float h = acc[i][j] * sc[j] + bs[j];
                r[j] = (h >= 0.f) ? h : 0.01f * h;
            }
            float* dst = &g_padded[((size_t)bb * T_ + t) * C_ + c0];
            *(float4*)dst       = make_float4(r[0], r[1], r[2], r[3]);
            *(float4*)(dst + 4) = make_float4(r[4], r[5], r[6], r[7]);
        }
    }
}

// ---------------------------------------------------------------------------
// Pass 1: per-row softmax max & inverse-denominator (online over key tiles).
// Grid (16, 32): 64-row query tiles per batch. 256 threads, 4x4 S microtile.
// ---------------------------------------------------------------------------
#define P1_SMEM_FLOATS (2 * 128 * 68)

__global__ void pass1_kernel(const int* __restrict__ lengths) {
    extern __shared__ float sm[];
    float* Qt = sm;                // [k 128][row 64] pitch 68
    float* Kt = sm + 128 * 68;
    const int b = blockIdx.y;
    const int len = lengths[b];
    const int tile0 = blockIdx.x * 64;
    if (tile0 >= len) return;

    const int tid = threadIdx.x;
    const int ty = tid >> 4, tx = tid & 15;
    const int r0 = ty * 4, s0 = tx * 4;
    const float* pb = g_padded + (size_t)b * T_ * C_;

    // load Q tile transposed
#pragma unroll
    for (int it = 0; it < 32; it++) {
        int idx = tid + it * 256;              // 64*128 = 8192
        int k = idx & 127, r = idx >> 7;
        Qt[k * 68 + r] = pb[(size_t)(tile0 + r) * C_ + k];
    }

    float m_run[4], d_run[4];
#pragma unroll
    for (int i = 0; i < 4; i++) { m_run[i] = -1e30f; d_run[i] = 0.f; }

    const int nkt = (len + 63) >> 6;
    for (int kt = 0; kt < nkt; kt++) {
        __syncthreads();
#pragma unroll
        for (int it = 0; it < 32; it++) {
            int idx = tid + it * 256;
            int k = idx & 127, r = idx >> 7;
            Kt[k * 68 + r] = pb[(size_t)(kt * 64 + r) * C_ + k];
        }
        __syncthreads();

        float s4[4][4];
#pragma unroll
        for (int i = 0; i < 4; i++)
#pragma unroll
            for (int j = 0; j < 4; j++) s4[i][j] = 0.f;
#pragma unroll 16
        for (int k = 0; k < 128; k++) {
            float4 q  = *(const float4*)&Qt[k * 68 + r0];
            float4 kv = *(const float4*)&Kt[k * 68 + s0];
            float qa[4] = {q.x, q.y, q.z, q.w};
            float kb[4] = {kv.x, kv.y, kv.z, kv.w};
#pragma unroll
            for (int i = 0; i < 4; i++)
#pragma unroll
                for (int j = 0; j < 4; j++) s4[i][j] += qa[i] * kb[j];
        }
#pragma unroll
        for (int i = 0; i < 4; i++) {
            float tmax = -1e30f;
#pragma unroll
            for (int j = 0; j < 4; j++) tmax = fmaxf(tmax, s4[i][j] * SCL);
#pragma unroll
            for (int off = 8; off >= 1; off >>= 1)
                tmax = fmaxf(tmax, __shfl_xor_sync(0xffffffffu, tmax, off));
            float mnew = fmaxf(m_run[i], tmax);
            float ps = 0.f;
#pragma unroll
            for (int j = 0; j < 4; j++) ps += __expf(s4[i][j] * SCL - mnew);
#pragma unroll
            for (int off = 8; off >= 1; off >>= 1)
                ps += __shfl_xor_sync(0xffffffffu, ps, off);
            d_run[i] = d_run[i] * __expf(m_run[i] - mnew) + ps;
            m_run[i] = mnew;
        }
    }

    // finalize: analytic padding term for the (T - nkt*64) untouched columns
    if (tx == 0) {
        float extra = (float)(T_ - nkt * 64);
        bool haspad = (len < T_);
#pragma unroll
        for (int i = 0; i < 4; i++) {
            float m = m_run[i];
            float mf = haspad ? fmaxf(m, 0.f) : m;
            float d = d_run[i] * __expf(m - mf) + extra * __expf(-mf);
            int t = tile0 + r0 + i;
            g_m[b * T_ + t]    = mf;
            g_invd[b * T_ + t] = 1.f / d;
        }
    }
}

// ---------------------------------------------------------------------------
// Pass 2: recompute S, w = softmax + temp_attn, O += w @ V, gather to packed.
// ---------------------------------------------------------------------------
#define P2_SMEM_FLOATS (2 * 128 * 68 + 64 * 132 + 64 * 68 + 128)

__global__ void pass2_kernel(const int* __restrict__ lengths,
                             const float* __restrict__ temp_attn,
                             float* __restrict__ out) {
    extern __shared__ float sm[];
    float* Qt   = sm;                                  // [128][68]
    float* Kt   = Qt + 128 * 68;                       // [128][68]
    float* Ks   = Kt + 128 * 68;                       // [64][132] row-major
    float* Ps   = Ks + 64 * 132;                       // [64][68]
    float* sm_m = Ps + 64 * 68;                        // [64]
    float* sm_d = sm_m + 64;                           // [64]

    const int b = blockIdx.y;
    const int len = lengths[b];
    const int tile0 = blockIdx.x * 64;
    if (tile0 >= len) return;

    const int tid = threadIdx.x;
    const int ty = tid >> 4, tx = tid & 15;
    const int r0 = ty * 4, s0 = tx * 4, c0 = tx * 8;
    const float* pb = g_padded + (size_t)b * T_ * C_;

    int ro = 0;
    for (int i = 0; i < b; i++) ro += lengths[i];

#pragma unroll
    for (int it = 0; it < 32; it++) {
        int idx = tid + it * 256;
        int k = idx & 127, r = idx >> 7;
        Qt[k * 68 + r] = pb[(size_t)(tile0 + r) * C_ + k];
    }
    if (tid < 64) {
        sm_m[tid] = g_m[b * T_ + tile0 + tid];
        sm_d[tid] = g_invd[b * T_ + tile0 + tid];
    }

    float acc[4][8];
#pragma unroll
    for (int i = 0; i < 4; i++)
#pragma unroll
        for (int j = 0; j < 8; j++) acc[i][j] = 0.f;

    const float* tb = temp_attn + ((size_t)b * T_ + tile0) * T_;
    const int nkt = (len + 63) >> 6;

    for (int kt = 0; kt < nkt; kt++) {
        __syncthreads();
#pragma unroll
        for (int it = 0; it < 32; it++) {
            int idx = tid + it * 256;
            int k = idx & 127, r = idx >> 7;
            float v = pb[(size_t)(kt * 64 + r) * C_ + k];
            Kt[k * 68 + r]  = v;   // [k][s] for S
            Ks[r * 132 + k] = v;   // [s][c] for PV
        }
        __syncthreads();

        // S = Q K^T
        float s4[4][4];
#pragma unroll
        for (int i = 0; i < 4; i++)
#pragma unroll
            for (int j = 0; j < 4; j++) s4[i][j] = 0.f;
#pragma unroll 16
        for (int k = 0; k < 128; k++) {
            float4 q  = *(const float4*)&Qt[k * 68 + r0];
            float4 kv = *(const float4*)&Kt[k * 68 + s0];
            float qa[4] = {q.x, q.y, q.z, q.w};
            float kb[4] = {kv.x, kv.y, kv.z, kv.w};
#pragma unroll
            for (int i = 0; i < 4; i++)
#pragma unroll
                for (int j = 0; j < 4; j++) s4[i][j] += qa[i] * kb[j];
        }
        // w = exp(S*scl - m)/d + temp_attn   (no column mask: padded h rows are 0)
#pragma unroll
        for (int i = 0; i < 4; i++) {
            int t = r0 + i;
            float mi = sm_m[t], di = sm_d[t];
            float4 ta = *(const float4*)(tb + (size_t)t * T_ + kt * 64 + s0);
            float w0 = __expf(s4[i][0] * SCL - mi) * di + ta.x;
            float w1 = __expf(s4[i][1] * SCL - mi) * di + ta.y;
            float w2 = __expf(s4[i][2] * SCL - mi) * di + ta.z;
            float w3 = __expf(s4[i][3] * SCL - mi) * di + ta.w;
            float* pr = &Ps[t * 68 + s0];
            pr[0] = w0; pr[1] = w1; pr[2] = w2; pr[3] = w3;
        }
        __syncthreads();

        // O += P @ V  (V = K tile, row-major Ks)
#pragma unroll 8
        for (int s = 0; s < 64; s++) {
            float p0 = Ps[(r0 + 0) * 68 + s];
            float p1 = Ps[(r0 + 1) * 68 + s];
            float p2 = Ps[(r0 + 2) * 68 + s];
            float p3 = Ps[(r0 + 3) * 68 + s];
            float4 ka = *(const float4*)&Ks[s * 132 + c0];
            float4 kb = *(const float4*)&Ks[s * 132 + c0 + 4];
            float kv[8] = {ka.x, ka.y, ka.z, ka.w, kb.x, kb.y, kb.z, kb.w};
#pragma unroll
            for (int j = 0; j < 8; j++) {
                acc[0][j] += p0 * kv[j];
                acc[1][j] += p1 * kv[j];
                acc[2][j] += p2 * kv[j];
                acc[3][j] += p3 * kv[j];
            }
        }
    }

    // gather valid rows to packed output
#pragma unroll
    for (int i = 0; i < 4; i++) {
        int t = tile0 + r0 + i;
        if (t < len) {
            float* dst = out + ((size_t)(ro + t)) * C_ + c0;
            *(float4*)dst       = make_float4(acc[i][0], acc[i][1], acc[i][2], acc[i][3]);
            *(float4*)(dst + 4) = make_float4(acc[i][4], acc[i][5], acc[i][6], acc[i][7]);
        }
    }
}

// ---------------------------------------------------------------------------
// Stat branch: [32,64] @ [64,64]^T + BN + leaky
// ---------------------------------------------------------------------------
__global__ void stat_kernel(const float* __restrict__ xs, const float* __restrict__ W2,
                            const float* __restrict__ b2, const float* __restrict__ g2,
                            const float* __restrict__ be2, const float* __restrict__ mu2,
                            const float* __restrict__ v2, float* __restrict__ out) {
    __shared__ float xrow[64];
    int b = blockIdx.x, c = threadIdx.x;
    if (c < 64) xrow[c] = xs[b * 64 + c];
    __syncthreads();
    float a = 0.f;
#pragma unroll 8
    for (int k = 0; k < 64; k++) a += xrow[k] * W2[c * 64 + k];
    float s = g2[c] * rsqrtf(v2[c] + EPS_);
    float h = (a + b2[c] - mu2[c]) * s + be2[c];
    out[b * 64 + c] = (h >= 0.f) ? h : 0.01f * h;
}

// ---------------------------------------------------------------------------
extern "C" void kernel_launch(void* const* d_in, const int* in_sizes, int n_in,
                              void* d_out, int out_size) {
    const float* x_temp    = (const float*)d_in[0];
    const float* x_stat    = (const float*)d_in[1];
    const float* temp_attn = (const float*)d_in[2];
    // d_in[3] = mask_repeat (unused: reconstructed implicitly from lengths)
    const int*   lengths   = (const int*)d_in[4];
    const int*   batch_idx = (const int*)d_in[5];
    const int*   pos_idx   = (const int*)d_in[6];
    const float* W1 = (const float*)d_in[7];
    const float* b1 = (const float*)d_in[8];
    const float* g1 = (const float*)d_in[9];
    const float* be1= (const float*)d_in[10];
    const float* mu1= (const float*)d_in[11];
    const float* v1 = (const float*)d_in[12];
    const float* W2 = (const float*)d_in[13];
    const float* b2 = (const float*)d_in[14];
    const float* g2 = (const float*)d_in[15];
    const float* be2= (const float*)d_in[16];
    const float* mu2= (const float*)d_in[17];
    const float* v2 = (const float*)d_in[18];

    const int N = in_sizes[0] / 128;
    float* out = (float*)d_out;

    cudaFuncSetAttribute(pass1_kernel, cudaFuncAttributeMaxDynamicSharedMemorySize,
                         P1_SMEM_FLOATS * 4);
    cudaFuncSetAttribute(pass2_kernel, cudaFuncAttributeMaxDynamicSharedMemorySize,
                         P2_SMEM_FLOATS * 4);

    k1_kernel<<<(N + 63) / 64, 256>>>(x_temp, x_stat, batch_idx, pos_idx,
                                      W1, b1, g1, be1, mu1, v1, N);
    dim3 grid(T_ / 64, B_);
    pass1_kernel<<<grid, 256, P1_SMEM_FLOATS * 4>>>(lengths);
    pass2_kernel<<<grid, 256, P2_SMEM_FLOATS * 4>>>(lengths, temp_attn, out);
    stat_kernel<<<B_, 64>>>(x_stat, W2, b2, g2, be2, mu2, v2, out + (size_t)N * C_);
}

// round 5
// speedup vs baseline: 2.4956x; 2.4956x over previous
#include <cuda_runtime.h>
#include <cstdint>

#define B_   32
#define T_   1024
#define C_   128
#define EPS_ 1e-5f
#define SCL  0.08838834764831845f   // 1/sqrt(128)

// Scratch (device globals; deterministic: valid slots rewritten identically each launch,
// invalid slots never read where uninitialized-by-this-launch).
__device__ float g_padded[B_ * T_ * C_];          // 16 MB
__device__ float g_m[B_ * T_];
__device__ float g_invd[B_ * T_];
__device__ float g_S[(size_t)B_ * T_ * T_];       // 134 MB raw scaled logits

// ---------------------------------------------------------------------------
// helpers: tf32 rounding + warp mma
// ---------------------------------------------------------------------------
__device__ __forceinline__ float f2tf(float x) {
    uint32_t u;
    asm("cvt.rna.tf32.f32 %0, %1;" : "=r"(u) : "f"(x));
    return __uint_as_float(u);
}

__device__ __forceinline__ void mma_tf32(float* c, const float* a, const float* b) {
    const uint32_t* A = reinterpret_cast<const uint32_t*>(a);
    const uint32_t* Bp = reinterpret_cast<const uint32_t*>(b);
    asm volatile(
        "mma.sync.aligned.m16n8k8.row.col.f32.tf32.tf32.f32 "
        "{%0,%1,%2,%3}, {%4,%5,%6,%7}, {%8,%9}, {%0,%1,%2,%3};\n"
        : "+f"(c[0]), "+f"(c[1]), "+f"(c[2]), "+f"(c[3])
        : "r"(A[0]), "r"(A[1]), "r"(A[2]), "r"(A[3]), "r"(Bp[0]), "r"(Bp[1]));
}

// ---------------------------------------------------------------------------
// K1: h = leaky(BN(concat(x_temp, x_stat[bidx]) @ W1^T + b1)), scatter to padded
// (unchanged fp32 SIMT from R3)
// ---------------------------------------------------------------------------
__global__ void k1_kernel(const float* __restrict__ x_temp, const float* __restrict__ x_stat,
                          const int* __restrict__ bidx, const int* __restrict__ pidx,
                          const float* __restrict__ W1, const float* __restrict__ b1,
                          const float* __restrict__ g1, const float* __restrict__ be1,
                          const float* __restrict__ mu1, const float* __restrict__ v1,
                          int N) {
    __shared__ float Xt[32 * 68];
    __shared__ float Ws[32 * 132];
    const int n0  = blockIdx.x * 64;
    const int tid = threadIdx.x;
    const int ty  = tid >> 4, tx = tid & 15;
    const int r0  = ty * 4, c0 = tx * 8;

    float acc[4][8];
#pragma unroll
    for (int i = 0; i < 4; i++)
#pragma unroll
        for (int j = 0; j < 8; j++) acc[i][j] = 0.f;

    for (int kt = 0; kt < 192; kt += 32) {
        __syncthreads();
#pragma unroll
        for (int it = 0; it < 8; it++) {
            int idx = tid + it * 256;
            int k = idx & 31, r = idx >> 5;
            int n = n0 + r, kg = kt + k;
            float v = 0.f;
            if (n < N)
                v = (kg < 128) ? x_temp[(size_t)n * 128 + kg]
                               : x_stat[bidx[n] * 64 + (kg - 128)];
            Xt[k * 68 + r] = v;
        }
#pragma unroll
        for (int it = 0; it < 16; it++) {
            int idx = tid + it * 256;
            int k = idx & 31, c = idx >> 5;
            Ws[k * 132 + c] = W1[c * 192 + kt + k];
        }
        __syncthreads();
#pragma unroll 8
        for (int k = 0; k < 32; k++) {
            float4 xv = *(const float4*)&Xt[k * 68 + r0];
            float4 w0 = *(const float4*)&Ws[k * 132 + c0];
            float4 w1 = *(const float4*)&Ws[k * 132 + c0 + 4];
            float xa[4] = {xv.x, xv.y, xv.z, xv.w};
            float wb[8] = {w0.x, w0.y, w0.z, w0.w, w1.x, w1.y, w1.z, w1.w};
#pragma unroll
            for (int i = 0; i < 4; i++)
#pragma unroll
                for (int j = 0; j < 8; j++) acc[i][j] += xa[i] * wb[j];
        }
    }

    float sc[8], bs[8];
#pragma unroll
    for (int j = 0; j < 8; j++) {
        int c = c0 + j;
        float s = g1[c] * rsqrtf(v1[c] + EPS_);
        sc[j] = s;
        bs[j] = (b1[c] - mu1[c]) * s + be1[c];
    }
#pragma unroll
    for (int i = 0; i < 4; i++) {
        int n = n0 + r0 + i;
        if (n < N) {
            int bb = bidx[n], t = pidx[n];
            float r[8];
#pragma unroll
            for (int j = 0; j < 8; j++) {
                float h = acc[i][j] * sc[j] + bs[j];
                r[j] = (h >= 0.f) ? h : 0.01f * h;
            }
            float* dst = &g_padded[((size_t)bb * T_ + t) * C_ + c0];
            *(float4*)dst       = make_float4(r[0], r[1], r[2], r[3]);
            *(float4*)(dst + 4) = make_float4(r[4], r[5], r[6], r[7]);
        }
    }
}

// ---------------------------------------------------------------------------
// Pass 1 (tf32 MMA): S = Q K^T * SCL  -> g_S ; online row (m, 1/d) -> g_m, g_invd
// 64x64 S tile per key step; block = 256 thr = 8 warps (warp_m 0..3 x warp_n 0..1)
// ---------------------------------------------------------------------------
#define QK_PITCH 132
#define P1_SMEM_FLOATS (2 * 64 * QK_PITCH + 128 + 128 + 64 + 64)

__global__ void pass1_mma(const int* __restrict__ lengths) {
    extern __shared__ float sm[];
    float* Qs    = sm;                         // [64][132]
    float* Ks    = Qs + 64 * QK_PITCH;         // [64][132]
    float* pmax  = Ks + 64 * QK_PITCH;         // [2][64]
    float* psum  = pmax + 128;                 // [2][64]
    float* m_run = psum + 128;                 // [64]
    float* d_run = m_run + 64;                 // [64]

    const int b = blockIdx.y;
    const int len = lengths[b];
    const int tile0 = blockIdx.x * 64;
    if (tile0 >= len) return;

    const int tid  = threadIdx.x;
    const int wid  = tid >> 5, lane = tid & 31;
    const int wm   = wid >> 1, wn = wid & 1;
    const int g    = lane >> 2, tg = lane & 3;
    const int qr   = wm * 16 + g;              // first of the two fragment rows
    const float* pb = g_padded + (size_t)b * T_ * C_;

    if (tid < 64) { m_run[tid] = -1e30f; d_run[tid] = 0.f; }

    // load Q tile (tf32-rounded), rows tile0..tile0+63
#pragma unroll
    for (int it = 0; it < 8; it++) {
        int e = (tid + it * 256) * 4;
        int r = e >> 7, c = e & 127;
        float4 v = *(const float4*)&pb[(size_t)(tile0 + r) * C_ + c];
        *(float4*)&Qs[r * QK_PITCH + c] =
            make_float4(f2tf(v.x), f2tf(v.y), f2tf(v.z), f2tf(v.w));
    }
    __syncthreads();

    // Q fragments in registers (loop-invariant)
    float qf[16][4];
#pragma unroll
    for (int kk = 0; kk < 16; kk++) {
        int cb = kk * 8 + tg;
        qf[kk][0] = Qs[qr * QK_PITCH + cb];
        qf[kk][1] = Qs[(qr + 8) * QK_PITCH + cb];
        qf[kk][2] = Qs[qr * QK_PITCH + cb + 4];
        qf[kk][3] = Qs[(qr + 8) * QK_PITCH + cb + 4];
    }

    const int nkt = (len + 63) >> 6;
    const size_t srow = (size_t)(b * T_ + tile0) * T_;

    for (int kt = 0; kt < nkt; kt++) {
        __syncthreads();
        // load K tile
#pragma unroll
        for (int it = 0; it < 8; it++) {
            int e = (tid + it * 256) * 4;
            int r = e >> 7, c = e & 127;
            float4 v = *(const float4*)&pb[(size_t)(kt * 64 + r) * C_ + c];
            *(float4*)&Ks[r * QK_PITCH + c] =
                make_float4(f2tf(v.x), f2tf(v.y), f2tf(v.z), f2tf(v.w));
        }
        __syncthreads();

        // S = Q K^T : each warp 16 rows x 32 cols (4 n-chunks of 8)
        float c4[4][4];
#pragma unroll
        for (int ch = 0; ch < 4; ch++)
#pragma unroll
            for (int i = 0; i < 4; i++) c4[ch][i] = 0.f;

#pragma unroll
        for (int kk = 0; kk < 16; kk++) {
            int kb = kk * 8 + tg;
#pragma unroll
            for (int ch = 0; ch < 4; ch++) {
                int nc = wn * 32 + ch * 8 + g;   // key index
                float bb[2] = { Ks[nc * QK_PITCH + kb], Ks[nc * QK_PITCH + kb + 4] };
                mma_tf32(c4[ch], qf[kk], bb);
            }
        }
        // scale
#pragma unroll
        for (int ch = 0; ch < 4; ch++)
#pragma unroll
            for (int i = 0; i < 4; i++) c4[ch][i] *= SCL;

        // per-row tile max (rows qr, qr+8)
        float mA = -1e30f, mB = -1e30f;
#pragma unroll
        for (int ch = 0; ch < 4; ch++) {
            mA = fmaxf(mA, fmaxf(c4[ch][0], c4[ch][1]));
            mB = fmaxf(mB, fmaxf(c4[ch][2], c4[ch][3]));
        }
#pragma unroll
        for (int off = 1; off <= 2; off <<= 1) {
            mA = fmaxf(mA, __shfl_xor_sync(0xffffffffu, mA, off));
            mB = fmaxf(mB, __shfl_xor_sync(0xffffffffu, mB, off));
        }
        if (tg == 0) { pmax[wn * 64 + qr] = mA; pmax[wn * 64 + qr + 8] = mB; }
        __syncthreads();

        float mnA = fmaxf(m_run[qr],     fmaxf(pmax[qr],     pmax[64 + qr]));
        float mnB = fmaxf(m_run[qr + 8], fmaxf(pmax[qr + 8], pmax[64 + qr + 8]));

        float pA = 0.f, pB = 0.f;
#pragma unroll
        for (int ch = 0; ch < 4; ch++) {
            pA += __expf(c4[ch][0] - mnA) + __expf(c4[ch][1] - mnA);
            pB += __expf(c4[ch][2] - mnB) + __expf(c4[ch][3] - mnB);
        }
#pragma unroll
        for (int off = 1; off <= 2; off <<= 1) {
            pA += __shfl_xor_sync(0xffffffffu, pA, off);
            pB += __shfl_xor_sync(0xffffffffu, pB, off);
        }
        if (tg == 0) { psum[wn * 64 + qr] = pA; psum[wn * 64 + qr + 8] = pB; }

        // store scaled S (float2 -> full 32B sectors)
#pragma unroll
        for (int ch = 0; ch < 4; ch++) {
            int cc = kt * 64 + wn * 32 + ch * 8 + 2 * tg;
            *(float2*)&g_S[srow + (size_t)qr * T_ + cc] =
                make_float2(c4[ch][0], c4[ch][1]);
            *(float2*)&g_S[srow + (size_t)(qr + 8) * T_ + cc] =
                make_float2(c4[ch][2], c4[ch][3]);
        }
        __syncthreads();

        if (tid < 64) {
            int r = tid;
            float mn = fmaxf(m_run[r], fmaxf(pmax[r], pmax[64 + r]));
            d_run[r] = d_run[r] * __expf(m_run[r] - mn) + psum[r] + psum[64 + r];
            m_run[r] = mn;
        }
    }

    __syncthreads();
    if (tid < 64) {
        float m = m_run[tid], d = d_run[tid];
        bool haspad = (len < T_);
        float extra = (float)(T_ - nkt * 64);
        float mf = haspad ? fmaxf(m, 0.f) : m;
        float dd = d * __expf(m - mf) + extra * __expf(-mf);
        int t = tile0 + tid;
        g_m[b * T_ + t]    = mf;
        g_invd[b * T_ + t] = 1.f / dd;
    }
}

// ---------------------------------------------------------------------------
// Pass 2 (tf32 MMA): P = exp(S - m)*invd + temp_attn ; out = P @ V (V = padded)
// Each warp: 16 q-rows x 64 out-channels. No QK recompute.
// ---------------------------------------------------------------------------
#define V_PITCH 136
#define P_PITCH 68
#define P2_SMEM_FLOATS (64 * V_PITCH + 64 * P_PITCH + 64 + 64)

__global__ void __launch_bounds__(256, 2) pass2_mma(const int* __restrict__ lengths,
                                                    const float* __restrict__ temp_attn,
                                                    float* __restrict__ out) {
    extern __shared__ float sm[];
    float* Ks   = sm;                          // [64][136] V tile (tf32)
    float* Ps   = Ks + 64 * V_PITCH;           // [64][68]  P tile (tf32)
    float* sm_m = Ps + 64 * P_PITCH;           // [64]
    float* sm_d = sm_m + 64;                   // [64]

    const int b = blockIdx.y;
    const int len = lengths[b];
    const int tile0 = blockIdx.x * 64;
    if (tile0 >= len) return;

    const int tid  = threadIdx.x;
    const int wid  = tid >> 5, lane = tid & 31;
    const int wm   = wid >> 1, wn = wid & 1;
    const int g    = lane >> 2, tg = lane & 3;
    const int qr   = wm * 16 + g;
    const float* pb = g_padded + (size_t)b * T_ * C_;

    int ro = 0;
    for (int i = 0; i < b; i++) ro += lengths[i];

    if (tid < 64) {
        sm_m[tid] = g_m[b * T_ + tile0 + tid];
        sm_d[tid] = g_invd[b * T_ + tile0 + tid];
    }

    float acc[8][4];
#pragma unroll
    for (int ch = 0; ch < 8; ch++)
#pragma unroll
        for (int i = 0; i < 4; i++) acc[ch][i] = 0.f;

    const float* tb = temp_attn + ((size_t)b * T_ + tile0) * T_;
    const size_t srow = (size_t)(b * T_ + tile0) * T_;
    const int nkt = (len + 63) >> 6;

    for (int kt = 0; kt < nkt; kt++) {
        __syncthreads();
        // V tile (tf32), pitch 136 (conflict-free for PV B-fragment access)
#pragma unroll
        for (int it = 0; it < 8; it++) {
            int e = (tid + it * 256) * 4;
            int r = e >> 7, c = e & 127;
            float4 v = *(const float4*)&pb[(size_t)(kt * 64 + r) * C_ + c];
            *(float4*)&Ks[r * V_PITCH + c] =
                make_float4(f2tf(v.x), f2tf(v.y), f2tf(v.z), f2tf(v.w));
        }
        // P tile: read S, form softmax+temp, round to tf32
#pragma unroll
        for (int it = 0; it < 4; it++) {
            int e = (tid + it * 256) * 4;      // 0..4092 over 64x64
            int r = e >> 6, c = e & 63;
            float4 s = *(const float4*)&g_S[srow + (size_t)r * T_ + kt * 64 + c];
            float4 ta = *(const float4*)&tb[(size_t)r * T_ + kt * 64 + c];
            float mi = sm_m[r], di = sm_d[r];
            *(float4*)&Ps[r * P_PITCH + c] = make_float4(
                f2tf(__expf(s.x - mi) * di + ta.x),
                f2tf(__expf(s.y - mi) * di + ta.y),
                f2tf(__expf(s.z - mi) * di + ta.z),
                f2tf(__expf(s.w - mi) * di + ta.w));
        }
        __syncthreads();

        // out += P @ V : A = P rows (q), k = key; B = V (key, channel)
#pragma unroll
        for (int kk = 0; kk < 8; kk++) {
            int kb = kk * 8;
            float af[4];
            af[0] = Ps[qr * P_PITCH + kb + tg];
            af[1] = Ps[(qr + 8) * P_PITCH + kb + tg];
            af[2] = Ps[qr * P_PITCH + kb + tg + 4];
            af[3] = Ps[(qr + 8) * P_PITCH + kb + tg + 4];
#pragma unroll
            for (int ch = 0; ch < 8; ch++) {
                int nc = wn * 64 + ch * 8 + g;   // out channel
                float bb[2] = { Ks[(kb + tg) * V_PITCH + nc],
                                Ks[(kb + tg + 4) * V_PITCH + nc] };
                mma_tf32(acc[ch], af, bb);
            }
        }
    }

    // write packed output
    int tA = tile0 + qr, tB = tA + 8;
#pragma unroll
    for (int ch = 0; ch < 8; ch++) {
        int cc = wn * 64 + ch * 8 + 2 * tg;
        if (tA < len)
            *(float2*)&out[(size_t)(ro + tA) * C_ + cc] = make_float2(acc[ch][0], acc[ch][1]);
        if (tB < len)
            *(float2*)&out[(size_t)(ro + tB) * C_ + cc] = make_float2(acc[ch][2], acc[ch][3]);
    }
}

// ---------------------------------------------------------------------------
// Stat branch: [32,64] @ [64,64]^T + BN + leaky
// ---------------------------------------------------------------------------
__global__ void stat_kernel(const float* __restrict__ xs, const float* __restrict__ W2,
                            const float* __restrict__ b2, const float* __restrict__ g2,
                            const float* __restrict__ be2, const float* __restrict__ mu2,
                            const float* __restrict__ v2, float* __restrict__ out) {
    __shared__ float xrow[64];
    int b = blockIdx.x, c = threadIdx.x;
    if (c < 64) xrow[c] = xs[b * 64 + c];
    __syncthreads();
    float a = 0.f;
#pragma unroll 8
    for (int k = 0; k < 64; k++) a += xrow[k] * W2[c * 64 + k];
    float s = g2[c] * rsqrtf(v2[c] + EPS_);
    float h = (a + b2[c] - mu2[c]) * s + be2[c];
    out[b * 64 + c] = (h >= 0.f) ? h : 0.01f * h;
}

// ---------------------------------------------------------------------------
extern "C" void kernel_launch(void* const* d_in, const int* in_sizes, int n_in,
                              void* d_out, int out_size) {
    const float* x_temp    = (const float*)d_in[0];
    const float* x_stat    = (const float*)d_in[1];
    const float* temp_attn = (const float*)d_in[2];
    // d_in[3] = mask_repeat (unused; implicit from lengths)
    const int*   lengths   = (const int*)d_in[4];
    const int*   batch_idx = (const int*)d_in[5];
    const int*   pos_idx   = (const int*)d_in[6];
    const float* W1 = (const float*)d_in[7];
    const float* b1 = (const float*)d_in[8];
    const float* g1 = (const float*)d_in[9];
    const float* be1= (const float*)d_in[10];
    const float* mu1= (const float*)d_in[11];
    const float* v1 = (const float*)d_in[12];
    const float* W2 = (const float*)d_in[13];
    const float* b2 = (const float*)d_in[14];
    const float* g2 = (const float*)d_in[15];
    const float* be2= (const float*)d_in[16];
    const float* mu2= (const float*)d_in[17];
    const float* v2 = (const float*)d_in[18];

    const int N = in_sizes[0] / 128;
    float* out = (float*)d_out;

    cudaFuncSetAttribute(pass1_mma, cudaFuncAttributeMaxDynamicSharedMemorySize,
                         P1_SMEM_FLOATS * 4);
    cudaFuncSetAttribute(pass2_mma, cudaFuncAttributeMaxDynamicSharedMemorySize,
                         P2_SMEM_FLOATS * 4);

    k1_kernel<<<(N + 63) / 64, 256>>>(x_temp, x_stat, batch_idx, pos_idx,
                                      W1, b1, g1, be1, mu1, v1, N);
    dim3 grid(T_ / 64, B_);
    pass1_mma<<<grid, 256, P1_SMEM_FLOATS * 4>>>(lengths);
    pass2_mma<<<grid, 256, P2_SMEM_FLOATS * 4>>>(lengths, temp_attn, out);
    stat_kernel<<<B_, 64>>>(x_stat, W2, b2, g2, be2, mu2, v2, out + (size_t)N * C_);
}

// round 6
// speedup vs baseline: 2.5421x; 1.0186x over previous
#include <cuda_runtime.h>
#include <cstdint>

#define B_   32
#define T_   1024
#define C_   128
#define EPS_ 1e-5f
#define SCL  0.08838834764831845f          // 1/sqrt(128)
#define K2E  0.1275187502506137f           // SCL * log2(e)

// Scratch (deterministic: valid slots rewritten identically each launch;
// zero-initialized padded slots never written).
__device__ float g_padded[B_ * T_ * C_];   // 16 MB

// ---------------------------------------------------------------------------
__device__ __forceinline__ float f2tf(float x) {
    uint32_t u;
    asm("cvt.rna.tf32.f32 %0, %1;" : "=r"(u) : "f"(x));
    return __uint_as_float(u);
}
__device__ __forceinline__ float ex2(float x) {
    float r;
    asm("ex2.approx.f32 %0, %1;" : "=f"(r) : "f"(x));
    return r;
}
__device__ __forceinline__ void mma_tf32(float* c, const float* a, const float* b) {
    const uint32_t* A = reinterpret_cast<const uint32_t*>(a);
    const uint32_t* Bp = reinterpret_cast<const uint32_t*>(b);
    asm volatile(
        "mma.sync.aligned.m16n8k8.row.col.f32.tf32.tf32.f32 "
        "{%0,%1,%2,%3}, {%4,%5,%6,%7}, {%8,%9}, {%0,%1,%2,%3};\n"
        : "+f"(c[0]), "+f"(c[1]), "+f"(c[2]), "+f"(c[3])
        : "r"(A[0]), "r"(A[1]), "r"(A[2]), "r"(A[3]), "r"(Bp[0]), "r"(Bp[1]));
}

// ---------------------------------------------------------------------------
// K1: h = leaky(BN(concat(x_temp, x_stat[bidx]) @ W1^T + b1)), scatter to padded
// ---------------------------------------------------------------------------
__global__ void k1_kernel(const float* __restrict__ x_temp, const float* __restrict__ x_stat,
                          const int* __restrict__ bidx, const int* __restrict__ pidx,
                          const float* __restrict__ W1, const float* __restrict__ b1,
                          const float* __restrict__ g1, const float* __restrict__ be1,
                          const float* __restrict__ mu1, const float* __restrict__ v1,
                          int N) {
    __shared__ float Xt[32 * 68];
    __shared__ float Ws[32 * 132];
    const int n0  = blockIdx.x * 64;
    const int tid = threadIdx.x;
    const int ty  = tid >> 4, tx = tid & 15;
    const int r0  = ty * 4, c0 = tx * 8;

    float acc[4][8];
#pragma unroll
    for (int i = 0; i < 4; i++)
#pragma unroll
        for (int j = 0; j < 8; j++) acc[i][j] = 0.f;

    for (int kt = 0; kt < 192; kt += 32) {
        __syncthreads();
#pragma unroll
        for (int it = 0; it < 8; it++) {
            int idx = tid + it * 256;
            int k = idx & 31, r = idx >> 5;
            int n = n0 + r, kg = kt + k;
            float v = 0.f;
            if (n < N)
                v = (kg < 128) ? x_temp[(size_t)n * 128 + kg]
                               : x_stat[bidx[n] * 64 + (kg - 128)];
            Xt[k * 68 + r] = v;
        }
#pragma unroll
        for (int it = 0; it < 16; it++) {
            int idx = tid + it * 256;
            int k = idx & 31, c = idx >> 5;
            Ws[k * 132 + c] = W1[c * 192 + kt + k];
        }
        __syncthreads();
#pragma unroll 8
        for (int k = 0; k < 32; k++) {
            float4 xv = *(const float4*)&Xt[k * 68 + r0];
            float4 w0 = *(const float4*)&Ws[k * 132 + c0];
            float4 w1 = *(const float4*)&Ws[k * 132 + c0 + 4];
            float xa[4] = {xv.x, xv.y, xv.z, xv.w};
            float wb[8] = {w0.x, w0.y, w0.z, w0.w, w1.x, w1.y, w1.z, w1.w};
#pragma unroll
            for (int i = 0; i < 4; i++)
#pragma unroll
                for (int j = 0; j < 8; j++) acc[i][j] += xa[i] * wb[j];
        }
    }

    float sc[8], bs[8];
#pragma unroll
    for (int j = 0; j < 8; j++) {
        int c = c0 + j;
        float s = g1[c] * rsqrtf(v1[c] + EPS_);
        sc[j] = s;
        bs[j] = (b1[c] - mu1[c]) * s + be1[c];
    }
#pragma unroll
    for (int i = 0; i < 4; i++) {
        int n = n0 + r0 + i;
        if (n < N) {
            int bb = bidx[n], t = pidx[n];
            float r[8];
#pragma unroll
            for (int j = 0; j < 8; j++) {
                float h = acc[i][j] * sc[j] + bs[j];
                r[j] = (h >= 0.f) ? h : 0.01f * h;
            }
            float* dst = &g_padded[((size_t)bb * T_ + t) * C_ + c0];
            *(float4*)dst       = make_float4(r[0], r[1], r[2], r[3]);
            *(float4*)(dst + 4) = make_float4(r[4], r[5], r[6], r[7]);
        }
    }
}

// ---------------------------------------------------------------------------
// Fused attention (single pass, tf32 MMA):
//   per key tile: S = QK^T, E = exp(S*SCL) [no max-sub: |logits| bounded],
//   d += rowsum(E), accS += E@V, accT += temp@V
//   out = accS * (1/(d + pad)) + accT
// Block: 256 thr, 8 warps (wm 0..3 x wn 0..1). Warp: 16 q-rows.
//   QK: warp covers 16 rows x 32 keys (wn splits 64 keys).
//   PV: warp covers 16 rows x 64 channels (wn splits 128 channels).
// ---------------------------------------------------------------------------
#define QS_PITCH 132
#define KS_PITCH 136
#define PS_PITCH 68
#define AT_SMEM_FLOATS (64*QS_PITCH + 64*KS_PITCH + 64*PS_PITCH + 64*PS_PITCH + 64 + 128)

__global__ void __launch_bounds__(256, 1)
attn_fused(const int* __restrict__ lengths,
           const float* __restrict__ temp_attn,
           float* __restrict__ out) {
    extern __shared__ float sm[];
    float* Qs   = sm;                        // [64][132] Q (tf32)
    float* Ks   = Qs + 64 * QS_PITCH;        // [64][136] K/V tile (tf32)
    float* Ps   = Ks + 64 * KS_PITCH;        // [64][68]  E tile (tf32)
    float* Ts   = Ps + 64 * PS_PITCH;        // [64][68]  temp tile (tf32)
    float* dacc = Ts + 64 * PS_PITCH;        // [64] running denominators
    float* psum = dacc + 64;                 // [2][64] per-tile partial sums
    float* inv  = psum;                      // reused in epilogue

    const int b = blockIdx.y;
    const int len = lengths[b];
    const int tile0 = blockIdx.x * 64;
    if (tile0 >= len) return;

    const int tid  = threadIdx.x;
    const int wid  = tid >> 5, lane = tid & 31;
    const int wm   = wid >> 1, wn = wid & 1;
    const int g    = lane >> 2, tg = lane & 3;
    const int qr   = wm * 16 + g;
    const float* pb = g_padded + (size_t)b * T_ * C_;

    int ro = 0;
    for (int i = 0; i < b; i++) ro += lengths[i];

    if (tid < 64) dacc[tid] = 0.f;

    // load Q tile (tf32)
#pragma unroll
    for (int it = 0; it < 8; it++) {
        int e = (tid + it * 256) * 4;
        int r = e >> 7, c = e & 127;
        float4 v = *(const float4*)&pb[(size_t)(tile0 + r) * C_ + c];
        *(float4*)&Qs[r * QS_PITCH + c] =
            make_float4(f2tf(v.x), f2tf(v.y), f2tf(v.z), f2tf(v.w));
    }

    float accS[8][4], accT[8][4];
#pragma unroll
    for (int ch = 0; ch < 8; ch++)
#pragma unroll
        for (int i = 0; i < 4; i++) { accS[ch][i] = 0.f; accT[ch][i] = 0.f; }

    const float* tb = temp_attn + ((size_t)b * T_ + tile0) * T_;
    const int nkt = (len + 63) >> 6;

    for (int kt = 0; kt < nkt; kt++) {
        __syncthreads();
        // K/V tile (tf32): serves QK B-frags and PV B-frags (pitch 136, CF both)
#pragma unroll
        for (int it = 0; it < 8; it++) {
            int e = (tid + it * 256) * 4;
            int r = e >> 7, c = e & 127;
            float4 v = *(const float4*)&pb[(size_t)(kt * 64 + r) * C_ + c];
            *(float4*)&Ks[r * KS_PITCH + c] =
                make_float4(f2tf(v.x), f2tf(v.y), f2tf(v.z), f2tf(v.w));
        }
        // temp tile (tf32)
#pragma unroll
        for (int it = 0; it < 4; it++) {
            int e = (tid + it * 256) * 4;
            int r = e >> 6, c = e & 63;
            float4 v = *(const float4*)&tb[(size_t)r * T_ + kt * 64 + c];
            *(float4*)&Ts[r * PS_PITCH + c] =
                make_float4(f2tf(v.x), f2tf(v.y), f2tf(v.z), f2tf(v.w));
        }
        __syncthreads();

        // S = Q K^T (warp: 16 rows x 32 keys)
        float c4[4][4];
#pragma unroll
        for (int ch = 0; ch < 4; ch++)
#pragma unroll
            for (int i = 0; i < 4; i++) c4[ch][i] = 0.f;
#pragma unroll
        for (int kk = 0; kk < 16; kk++) {
            int kb = kk * 8 + tg;
            float af[4];
            af[0] = Qs[qr * QS_PITCH + kb];
            af[1] = Qs[(qr + 8) * QS_PITCH + kb];
            af[2] = Qs[qr * QS_PITCH + kb + 4];
            af[3] = Qs[(qr + 8) * QS_PITCH + kb + 4];
#pragma unroll
            for (int ch = 0; ch < 4; ch++) {
                int nc = wn * 32 + ch * 8 + g;
                float bb[2] = { Ks[nc * KS_PITCH + kb], Ks[nc * KS_PITCH + kb + 4] };
                mma_tf32(c4[ch], af, bb);
            }
        }

        // E = exp(S*SCL) once; write to Ps; row partial sums
        float eA = 0.f, eB = 0.f;
#pragma unroll
        for (int ch = 0; ch < 4; ch++) {
            float e0 = ex2(c4[ch][0] * K2E);
            float e1 = ex2(c4[ch][1] * K2E);
            float e2 = ex2(c4[ch][2] * K2E);
            float e3 = ex2(c4[ch][3] * K2E);
            eA += e0 + e1;
            eB += e2 + e3;
            int cc = wn * 32 + ch * 8 + 2 * tg;
            *(float2*)&Ps[qr * PS_PITCH + cc]       = make_float2(f2tf(e0), f2tf(e1));
            *(float2*)&Ps[(qr + 8) * PS_PITCH + cc] = make_float2(f2tf(e2), f2tf(e3));
        }
#pragma unroll
        for (int off = 1; off <= 2; off <<= 1) {
            eA += __shfl_xor_sync(0xffffffffu, eA, off);
            eB += __shfl_xor_sync(0xffffffffu, eB, off);
        }
        if (tg == 0) { psum[wn * 64 + qr] = eA; psum[wn * 64 + qr + 8] = eB; }
        __syncthreads();

        // accS += E @ V ; accT += temp @ V  (shared B-frags)
#pragma unroll
        for (int kk = 0; kk < 8; kk++) {
            int kb = kk * 8;
            float aE[4], aT[4];
            aE[0] = Ps[qr * PS_PITCH + kb + tg];
            aE[1] = Ps[(qr + 8) * PS_PITCH + kb + tg];
            aE[2] = Ps[qr * PS_PITCH + kb + tg + 4];
            aE[3] = Ps[(qr + 8) * PS_PITCH + kb + tg + 4];
            aT[0] = Ts[qr * PS_PITCH + kb + tg];
            aT[1] = Ts[(qr + 8) * PS_PITCH + kb + tg];
            aT[2] = Ts[qr * PS_PITCH + kb + tg + 4];
            aT[3] = Ts[(qr + 8) * PS_PITCH + kb + tg + 4];
#pragma unroll
            for (int ch = 0; ch < 8; ch++) {
                int nc = wn * 64 + ch * 8 + g;
                float bb[2] = { Ks[(kb + tg) * KS_PITCH + nc],
                                Ks[(kb + tg + 4) * KS_PITCH + nc] };
                mma_tf32(accS[ch], aE, bb);
                mma_tf32(accT[ch], aT, bb);
            }
        }
        // fold this tile's partials into running denominator (post-barrier safe)
        if (tid < 64) dacc[tid] += psum[tid] + psum[64 + tid];
    }

    __syncthreads();
    if (tid < 64) {
        // padded columns beyond nkt*64 each contribute exp(0)=1; in-tile padded
        // keys already contributed E=1 naturally (h rows are zero -> S=0).
        float d = dacc[tid] + (float)(T_ - nkt * 64);
        inv[tid] = 1.f / d;
    }
    __syncthreads();

    const float iA = inv[qr], iB = inv[qr + 8];
    const int tA = tile0 + qr, tB = tA + 8;
#pragma unroll
    for (int ch = 0; ch < 8; ch++) {
        int cc = wn * 64 + ch * 8 + 2 * tg;
        if (tA < len)
            *(float2*)&out[(size_t)(ro + tA) * C_ + cc] =
                make_float2(accS[ch][0] * iA + accT[ch][0],
                            accS[ch][1] * iA + accT[ch][1]);
        if (tB < len)
            *(float2*)&out[(size_t)(ro + tB) * C_ + cc] =
                make_float2(accS[ch][2] * iB + accT[ch][2],
                            accS[ch][3] * iB + accT[ch][3]);
    }
}

// ---------------------------------------------------------------------------
// Stat branch: [32,64] @ [64,64]^T + BN + leaky
// ---------------------------------------------------------------------------
__global__ void stat_kernel(const float* __restrict__ xs, const float* __restrict__ W2,
                            const float* __restrict__ b2, const float* __restrict__ g2,
                            const float* __restrict__ be2, const float* __restrict__ mu2,
                            const float* __restrict__ v2, float* __restrict__ out) {
    __shared__ float xrow[64];
    int b = blockIdx.x, c = threadIdx.x;
    if (c < 64) xrow[c] = xs[b * 64 + c];
    __syncthreads();
    float a = 0.f;
#pragma unroll 8
    for (int k = 0; k < 64; k++) a += xrow[k] * W2[c * 64 + k];
    float s = g2[c] * rsqrtf(v2[c] + EPS_);
    float h = (a + b2[c] - mu2[c]) * s + be2[c];
    out[b * 64 + c] = (h >= 0.f) ? h : 0.01f * h;
}

// ---------------------------------------------------------------------------
extern "C" void kernel_launch(void* const* d_in, const int* in_sizes, int n_in,
                              void* d_out, int out_size) {
    const float* x_temp    = (const float*)d_in[0];
    const float* x_stat    = (const float*)d_in[1];
    const float* temp_attn = (const float*)d_in[2];
    // d_in[3] = mask_repeat (unused; implicit from lengths)
    const int*   lengths   = (const int*)d_in[4];
    const int*   batch_idx = (const int*)d_in[5];
    const int*   pos_idx   = (const int*)d_in[6];
    const float* W1 = (const float*)d_in[7];
    const float* b1 = (const float*)d_in[8];
    const float* g1 = (const float*)d_in[9];
    const float* be1= (const float*)d_in[10];
    const float* mu1= (const float*)d_in[11];
    const float* v1 = (const float*)d_in[12];
    const float* W2 = (const float*)d_in[13];
    const float* b2 = (const float*)d_in[14];
    const float* g2 = (const float*)d_in[15];
    const float* be2= (const float*)d_in[16];
    const float* mu2= (const float*)d_in[17];
    const float* v2 = (const float*)d_in[18];

    const int N = in_sizes[0] / 128;
    float* out = (float*)d_out;

    cudaFuncSetAttribute(attn_fused, cudaFuncAttributeMaxDynamicSharedMemorySize,
                         AT_SMEM_FLOATS * 4);

    k1_kernel<<<(N + 63) / 64, 256>>>(x_temp, x_stat, batch_idx, pos_idx,
                                      W1, b1, g1, be1, mu1, v1, N);
    dim3 grid(T_ / 64, B_);
    attn_fused<<<grid, 256, AT_SMEM_FLOATS * 4>>>(lengths, temp_attn, out);
    stat_kernel<<<B_, 64>>>(x_stat, W2, b2, g2, be2, mu2, v2, out + (size_t)N * C_);
}

// round 7
// speedup vs baseline: 4.0104x; 1.5776x over previous
#include <cuda_runtime.h>
#include <cstdint>

#define B_   32
#define T_   1024
#define C_   128
#define EPS_ 1e-5f
#define SCL  0.08838834764831845f          // 1/sqrt(128)
#define K2E  0.1275187502506137f           // SCL * log2(e)

// Scratch (deterministic: valid slots rewritten identically each launch;
// zero-initialized padded slots never written).
__device__ float g_padded[B_ * T_ * C_];   // 16 MB

// ---------------------------------------------------------------------------
__device__ __forceinline__ float f2tf(float x) {
    uint32_t u;
    asm("cvt.rna.tf32.f32 %0, %1;" : "=r"(u) : "f"(x));
    return __uint_as_float(u);
}
__device__ __forceinline__ float ex2(float x) {
    float r;
    asm("ex2.approx.f32 %0, %1;" : "=f"(r) : "f"(x));
    return r;
}
__device__ __forceinline__ void mma_tf32(float* c, const float* a, const float* b) {
    const uint32_t* A = reinterpret_cast<const uint32_t*>(a);
    const uint32_t* Bp = reinterpret_cast<const uint32_t*>(b);
    asm volatile(
        "mma.sync.aligned.m16n8k8.row.col.f32.tf32.tf32.f32 "
        "{%0,%1,%2,%3}, {%4,%5,%6,%7}, {%8,%9}, {%0,%1,%2,%3};\n"
        : "+f"(c[0]), "+f"(c[1]), "+f"(c[2]), "+f"(c[3])
        : "r"(A[0]), "r"(A[1]), "r"(A[2]), "r"(A[3]), "r"(Bp[0]), "r"(Bp[1]));
}

// ---------------------------------------------------------------------------
// K1 (tf32 MMA): h = leaky(BN(concat(x_temp, x_stat[bidx]) @ W1^T + b1))
// Block: 64 rows x 128 cols, K=192 in 3 chunks of 64. 8 warps (wm 0..3, wn 0..1).
// Xs: [row 64][k 64] pitch 68 (A-frags CF).  Ws: [col 128][k 64] pitch 68
// (coalesced global read along k, CF stores, CF B-frags: bank = 4g+tg).
// ---------------------------------------------------------------------------
#define K1_SMEM_FLOATS (64 * 68 + 128 * 68)

__global__ void __launch_bounds__(256, 2)
k1_mma(const float* __restrict__ x_temp, const float* __restrict__ x_stat,
       const int* __restrict__ bidx, const int* __restrict__ pidx,
       const float* __restrict__ W1, const float* __restrict__ b1,
       const float* __restrict__ g1, const float* __restrict__ be1,
       const float* __restrict__ mu1, const float* __restrict__ v1, int N) {
    extern __shared__ float sm[];
    float* Xs = sm;              // [64][68]
    float* Ws = sm + 64 * 68;    // [128][68]

    const int n0  = blockIdx.x * 64;
    const int tid = threadIdx.x;
    const int wid = tid >> 5, lane = tid & 31;
    const int wm  = wid >> 1, wn = wid & 1;
    const int g   = lane >> 2, tg = lane & 3;
    const int qr  = wm * 16 + g;

    float acc[8][4];
#pragma unroll
    for (int ch = 0; ch < 8; ch++)
#pragma unroll
        for (int i = 0; i < 4; i++) acc[ch][i] = 0.f;

    for (int ck = 0; ck < 3; ck++) {
        __syncthreads();
        // X tile: 64 rows x 64 k (float4 over k)
#pragma unroll
        for (int it = 0; it < 4; it++) {
            int e = (tid + it * 256) * 4;        // 0..4092
            int r = e >> 6, k4 = e & 63;
            int n = n0 + r;
            float4 v = make_float4(0.f, 0.f, 0.f, 0.f);
            if (n < N) {
                if (ck < 2)
                    v = *(const float4*)&x_temp[(size_t)n * 128 + ck * 64 + k4];
                else
                    v = *(const float4*)&x_stat[bidx[n] * 64 + k4];
            }
            *(float4*)&Xs[r * 68 + k4] =
                make_float4(f2tf(v.x), f2tf(v.y), f2tf(v.z), f2tf(v.w));
        }
        // W tile: 128 cols x 64 k (float4 over k, coalesced)
#pragma unroll
        for (int it = 0; it < 8; it++) {
            int e = (tid + it * 256) * 4;        // 0..8188
            int c = e >> 6, k4 = e & 63;
            float4 v = *(const float4*)&W1[(size_t)c * 192 + ck * 64 + k4];
            *(float4*)&Ws[c * 68 + k4] =
                make_float4(f2tf(v.x), f2tf(v.y), f2tf(v.z), f2tf(v.w));
        }
        __syncthreads();

#pragma unroll
        for (int kk = 0; kk < 8; kk++) {
            int kb = kk * 8 + tg;
            float af[4];
            af[0] = Xs[qr * 68 + kb];
            af[1] = Xs[(qr + 8) * 68 + kb];
            af[2] = Xs[qr * 68 + kb + 4];
            af[3] = Xs[(qr + 8) * 68 + kb + 4];
#pragma unroll
            for (int ch = 0; ch < 8; ch++) {
                int nc = wn * 64 + ch * 8 + g;
                float bb[2] = { Ws[nc * 68 + kb], Ws[nc * 68 + kb + 4] };
                mma_tf32(acc[ch], af, bb);
            }
        }
    }

    // epilogue: BN + leaky + scatter (thread: rows qr/qr+8, cols wn*64+ch*8+2tg,+1)
    int nA = n0 + qr, nB = n0 + qr + 8;
    int bbA = 0, ttA = 0, bbB = 0, ttB = 0;
    if (nA < N) { bbA = bidx[nA]; ttA = pidx[nA]; }
    if (nB < N) { bbB = bidx[nB]; ttB = pidx[nB]; }
#pragma unroll
    for (int ch = 0; ch < 8; ch++) {
        int c = wn * 64 + ch * 8 + 2 * tg;
        float s0 = g1[c]     * rsqrtf(v1[c]     + EPS_);
        float s1 = g1[c + 1] * rsqrtf(v1[c + 1] + EPS_);
        float o0 = (b1[c]     - mu1[c])     * s0 + be1[c];
        float o1 = (b1[c + 1] - mu1[c + 1]) * s1 + be1[c + 1];
        if (nA < N) {
            float h0 = acc[ch][0] * s0 + o0;
            float h1 = acc[ch][1] * s1 + o1;
            h0 = (h0 >= 0.f) ? h0 : 0.01f * h0;
            h1 = (h1 >= 0.f) ? h1 : 0.01f * h1;
            *(float2*)&g_padded[((size_t)bbA * T_ + ttA) * C_ + c] = make_float2(h0, h1);
        }
        if (nB < N) {
            float h2 = acc[ch][2] * s0 + o0;
            float h3 = acc[ch][3] * s1 + o1;
            h2 = (h2 >= 0.f) ? h2 : 0.01f * h2;
            h3 = (h3 >= 0.f) ? h3 : 0.01f * h3;
            *(float2*)&g_padded[((size_t)bbB * T_ + ttB) * C_ + c] = make_float2(h2, h3);
        }
    }
}

// ---------------------------------------------------------------------------
// Fused attention (single pass, tf32 MMA):
//   per key tile: S = QK^T, E = exp(S*SCL) (no max-sub: logits bounded),
//   d += rowsum(E), accS += E@V, accT += temp@V;  out = accS/(d+pad) + accT
// K/V tile pitch 140: QK B-frags (bank 12g+tg) and PV B-frags (12tg+g) both CF.
// __launch_bounds__(256,2): 2 CTAs/SM (2 x 105KB smem <= 228KB).
// ---------------------------------------------------------------------------
#define QS_PITCH 132
#define KS_PITCH 140
#define PS_PITCH 68
#define AT_SMEM_FLOATS (64*QS_PITCH + 64*KS_PITCH + 64*PS_PITCH + 64*PS_PITCH + 64 + 128)

__global__ void __launch_bounds__(256, 2)
attn_fused(const int* __restrict__ lengths,
           const float* __restrict__ temp_attn,
           float* __restrict__ out) {
    extern __shared__ float sm[];
    float* Qs   = sm;                        // [64][132] Q (tf32)
    float* Ks   = Qs + 64 * QS_PITCH;        // [64][140] K/V tile (tf32)
    float* Ps   = Ks + 64 * KS_PITCH;        // [64][68]  E tile (tf32)
    float* Ts   = Ps + 64 * PS_PITCH;        // [64][68]  temp tile (tf32)
    float* dacc = Ts + 64 * PS_PITCH;        // [64]
    float* psum = dacc + 64;                 // [2][64]
    float* inv  = psum;                      // reused in epilogue

    const int b = blockIdx.y;
    const int len = lengths[b];
    const int tile0 = blockIdx.x * 64;
    if (tile0 >= len) return;

    const int tid  = threadIdx.x;
    const int wid  = tid >> 5, lane = tid & 31;
    const int wm   = wid >> 1, wn = wid & 1;
    const int g    = lane >> 2, tg = lane & 3;
    const int qr   = wm * 16 + g;
    const float* pb = g_padded + (size_t)b * T_ * C_;

    int ro = 0;
    for (int i = 0; i < b; i++) ro += lengths[i];

    if (tid < 64) dacc[tid] = 0.f;

#pragma unroll
    for (int it = 0; it < 8; it++) {
        int e = (tid + it * 256) * 4;
        int r = e >> 7, c = e & 127;
        float4 v = *(const float4*)&pb[(size_t)(tile0 + r) * C_ + c];
        *(float4*)&Qs[r * QS_PITCH + c] =
            make_float4(f2tf(v.x), f2tf(v.y), f2tf(v.z), f2tf(v.w));
    }

    float accS[8][4], accT[8][4];
#pragma unroll
    for (int ch = 0; ch < 8; ch++)
#pragma unroll
        for (int i = 0; i < 4; i++) { accS[ch][i] = 0.f; accT[ch][i] = 0.f; }

    const float* tb = temp_attn + ((size_t)b * T_ + tile0) * T_;
    const int nkt = (len + 63) >> 6;

    for (int kt = 0; kt < nkt; kt++) {
        __syncthreads();
#pragma unroll
        for (int it = 0; it < 8; it++) {
            int e = (tid + it * 256) * 4;
            int r = e >> 7, c = e & 127;
            float4 v = *(const float4*)&pb[(size_t)(kt * 64 + r) * C_ + c];
            *(float4*)&Ks[r * KS_PITCH + c] =
                make_float4(f2tf(v.x), f2tf(v.y), f2tf(v.z), f2tf(v.w));
        }
#pragma unroll
        for (int it = 0; it < 4; it++) {
            int e = (tid + it * 256) * 4;
            int r = e >> 6, c = e & 63;
            float4 v = *(const float4*)&tb[(size_t)r * T_ + kt * 64 + c];
            *(float4*)&Ts[r * PS_PITCH + c] =
                make_float4(f2tf(v.x), f2tf(v.y), f2tf(v.z), f2tf(v.w));
        }
        __syncthreads();

        // S = Q K^T (warp: 16 rows x 32 keys)
        float c4[4][4];
#pragma unroll
        for (int ch = 0; ch < 4; ch++)
#pragma unroll
            for (int i = 0; i < 4; i++) c4[ch][i] = 0.f;
#pragma unroll
        for (int kk = 0; kk < 16; kk++) {
            int kb = kk * 8 + tg;
            float af[4];
            af[0] = Qs[qr * QS_PITCH + kb];
            af[1] = Qs[(qr + 8) * QS_PITCH + kb];
            af[2] = Qs[qr * QS_PITCH + kb + 4];
            af[3] = Qs[(qr + 8) * QS_PITCH + kb + 4];
#pragma unroll
            for (int ch = 0; ch < 4; ch++) {
                int nc = wn * 32 + ch * 8 + g;
                float bb[2] = { Ks[nc * KS_PITCH + kb], Ks[nc * KS_PITCH + kb + 4] };
                mma_tf32(c4[ch], af, bb);
            }
        }

        // E = exp(S*SCL); row partial sums; stage to Ps
        float eA = 0.f, eB = 0.f;
#pragma unroll
        for (int ch = 0; ch < 4; ch++) {
            float e0 = ex2(c4[ch][0] * K2E);
            float e1 = ex2(c4[ch][1] * K2E);
            float e2 = ex2(c4[ch][2] * K2E);
            float e3 = ex2(c4[ch][3] * K2E);
            eA += e0 + e1;
            eB += e2 + e3;
            int cc = wn * 32 + ch * 8 + 2 * tg;
            *(float2*)&Ps[qr * PS_PITCH + cc]       = make_float2(f2tf(e0), f2tf(e1));
            *(float2*)&Ps[(qr + 8) * PS_PITCH + cc] = make_float2(f2tf(e2), f2tf(e3));
        }
#pragma unroll
        for (int off = 1; off <= 2; off <<= 1) {
            eA += __shfl_xor_sync(0xffffffffu, eA, off);
            eB += __shfl_xor_sync(0xffffffffu, eB, off);
        }
        if (tg == 0) { psum[wn * 64 + qr] = eA; psum[wn * 64 + qr + 8] = eB; }
        __syncthreads();

        // accS += E @ V ; accT += temp @ V (shared B-frags)
#pragma unroll
        for (int kk = 0; kk < 8; kk++) {
            int kb = kk * 8;
            float aE[4], aT[4];
            aE[0] = Ps[qr * PS_PITCH + kb + tg];
            aE[1] = Ps[(qr + 8) * PS_PITCH + kb + tg];
            aE[2] = Ps[qr * PS_PITCH + kb + tg + 4];
            aE[3] = Ps[(qr + 8) * PS_PITCH + kb + tg + 4];
            aT[0] = Ts[qr * PS_PITCH + kb + tg];
            aT[1] = Ts[(qr + 8) * PS_PITCH + kb + tg];
            aT[2] = Ts[qr * PS_PITCH + kb + tg + 4];
            aT[3] = Ts[(qr + 8) * PS_PITCH + kb + tg + 4];
#pragma unroll
            for (int ch = 0; ch < 8; ch++) {
                int nc = wn * 64 + ch * 8 + g;
                float bb[2] = { Ks[(kb + tg) * KS_PITCH + nc],
                                Ks[(kb + tg + 4) * KS_PITCH + nc] };
                mma_tf32(accS[ch], aE, bb);
                mma_tf32(accT[ch], aT, bb);
            }
        }
        if (tid < 64) dacc[tid] += psum[tid] + psum[64 + tid];
    }

    __syncthreads();
    if (tid < 64) {
        float d = dacc[tid] + (float)(T_ - nkt * 64);   // pad cols contribute exp(0)=1
        inv[tid] = 1.f / d;
    }
    __syncthreads();

    const float iA = inv[qr], iB = inv[qr + 8];
    const int tA = tile0 + qr, tB = tA + 8;
#pragma unroll
    for (int ch = 0; ch < 8; ch++) {
        int cc = wn * 64 + ch * 8 + 2 * tg;
        if (tA < len)
            *(float2*)&out[(size_t)(ro + tA) * C_ + cc] =
                make_float2(accS[ch][0] * iA + accT[ch][0],
                            accS[ch][1] * iA + accT[ch][1]);
        if (tB < len)
            *(float2*)&out[(size_t)(ro + tB) * C_ + cc] =
                make_float2(accS[ch][2] * iB + accT[ch][2],
                            accS[ch][3] * iB + accT[ch][3]);
    }
}

// ---------------------------------------------------------------------------
// Stat branch: [32,64] @ [64,64]^T + BN + leaky
// ---------------------------------------------------------------------------
__global__ void stat_kernel(const float* __restrict__ xs, const float* __restrict__ W2,
                            const float* __restrict__ b2, const float* __restrict__ g2,
                            const float* __restrict__ be2, const float* __restrict__ mu2,
                            const float* __restrict__ v2, float* __restrict__ out) {
    __shared__ float xrow[64];
    int b = blockIdx.x, c = threadIdx.x;
    if (c < 64) xrow[c] = xs[b * 64 + c];
    __syncthreads();
    float a = 0.f;
#pragma unroll 8
    for (int k = 0; k < 64; k++) a += xrow[k] * W2[c * 64 + k];
    float s = g2[c] * rsqrtf(v2[c] + EPS_);
    float h = (a + b2[c] - mu2[c]) * s + be2[c];
    out[b * 64 + c] = (h >= 0.f) ? h : 0.01f * h;
}

// ---------------------------------------------------------------------------
extern "C" void kernel_launch(void* const* d_in, const int* in_sizes, int n_in,
                              void* d_out, int out_size) {
    const float* x_temp    = (const float*)d_in[0];
    const float* x_stat    = (const float*)d_in[1];
    const float* temp_attn = (const float*)d_in[2];
    // d_in[3] = mask_repeat (unused; implicit from lengths)
    const int*   lengths   = (const int*)d_in[4];
    const int*   batch_idx = (const int*)d_in[5];
    const int*   pos_idx   = (const int*)d_in[6];
    const float* W1 = (const float*)d_in[7];
    const float* b1 = (const float*)d_in[8];
    const float* g1 = (const float*)d_in[9];
    const float* be1= (const float*)d_in[10];
    const float* mu1= (const float*)d_in[11];
    const float* v1 = (const float*)d_in[12];
    const float* W2 = (const float*)d_in[13];
    const float* b2 = (const float*)d_in[14];
    const float* g2 = (const float*)d_in[15];
    const float* be2= (const float*)d_in[16];
    const float* mu2= (const float*)d_in[17];
    const float* v2 = (const float*)d_in[18];

    const int N = in_sizes[0] / 128;
    float* out = (float*)d_out;

    cudaFuncSetAttribute(k1_mma, cudaFuncAttributeMaxDynamicSharedMemorySize,
                         K1_SMEM_FLOATS * 4);
    cudaFuncSetAttribute(attn_fused, cudaFuncAttributeMaxDynamicSharedMemorySize,
                         AT_SMEM_FLOATS * 4);

    stat_kernel<<<B_, 64>>>(x_stat, W2, b2, g2, be2, mu2, v2, out + (size_t)N * C_);
    k1_mma<<<(N + 63) / 64, 256, K1_SMEM_FLOATS * 4>>>(x_temp, x_stat, batch_idx, pos_idx,
                                                       W1, b1, g1, be1, mu1, v1, N);
    dim3 grid(T_ / 64, B_);
    attn_fused<<<grid, 256, AT_SMEM_FLOATS * 4>>>(lengths, temp_attn, out);
}